// round 10
// baseline (speedup 1.0000x reference)
#include <cuda_runtime.h>
#include <cuda_fp16.h>
#include <math.h>

#define NB 2
#define NV 180
#define NR 32
#define NC 512
#define NPIX 512
#define PI_D 3.14159265358979323846

#define NRP (NR / 2)

// Filtered sinogram, image-pair packed: g_pack[((b*NV+v)*NRP+rp)*NC + i]
//   = half2( filt[b,v,2rp,i], filt[b,v,2rp+1,i] )
// +16 pad: staging reads overrun a row by up to 6 entries (never consumed).
__device__ __half2 g_pack[NB * NV * NRP * NC + 16];

// One block filters TWO consecutive real rows packed as one complex 512-pt FFT.
__global__ void __launch_bounds__(256) filter_kernel(const float* __restrict__ sino) {
    __shared__ float sre[512];
    __shared__ float sim[512];
    __shared__ float twr[256];
    __shared__ float twi[256];

    int tid = threadIdx.x;
    int base = blockIdx.x * 2 * NC;

    {
        float s, c;
        sincospif(-(float)tid * (1.0f / 256.0f), &s, &c);  // exp(-2*pi*i*tid/512)
        twr[tid] = c;
        twi[tid] = s;
    }
    sre[tid]       = sino[base + tid];
    sre[tid + 256] = sino[base + tid + 256];
    sim[tid]       = sino[base + NC + tid];
    sim[tid + 256] = sino[base + NC + tid + 256];
    __syncthreads();

    // ---- DIF forward ----
    {
        int step = 1;
        for (int len = 512; len >= 2; len >>= 1, step <<= 1) {
            int half = len >> 1;
            int grp = tid / half;
            int j = tid - grp * half;
            int i0 = grp * len + j;
            int i1 = i0 + half;
            int tj = j * step;
            float wr = twr[tj], wi = twi[tj];
            float ar = sre[i0], ai = sim[i0];
            float br = sre[i1], bi = sim[i1];
            sre[i0] = ar + br;
            sim[i0] = ai + bi;
            float dr = ar - br, di = ai - bi;
            sre[i1] = dr * wr - di * wi;
            sim[i1] = dr * wi + di * wr;
            if (len >= 128) __syncthreads();
            else __syncwarp();
        }
    }

    // ---- ramp multiply in bitrev slots (warp-local elements 2t, 2t+1) ----
    #pragma unroll
    for (int q = 0; q < 2; ++q) {
        int n = 2 * tid + q;
        int f = (int)(__brev((unsigned)n) >> 23);
        int m = min(f, 512 - f);
        float scale = (float)m * (2.0f / (512.0f * 512.0f));
        sre[n] *= scale;
        sim[n] *= scale;
    }
    __syncwarp();

    // ---- DIT inverse (conj twiddles) ----
    {
        int step = 256;
        for (int len = 2; len <= 512; len <<= 1, step >>= 1) {
            int half = len >> 1;
            int grp = tid / half;
            int j = tid - grp * half;
            int i0 = grp * len + j;
            int i1 = i0 + half;
            int tj = j * step;
            float wr = twr[tj], wi = -twi[tj];
            float ar = sre[i0], ai = sim[i0];
            float br = sre[i1], bi = sim[i1];
            float vr = br * wr - bi * wi;
            float vi = br * wi + bi * wr;
            sre[i0] = ar + vr;
            sim[i0] = ai + vi;
            sre[i1] = ar - vr;
            sim[i1] = ai - vi;
            if (len >= 64) __syncthreads();
            else __syncwarp();
        }
    }

    int pb = blockIdx.x * NC;
    g_pack[pb + tid]       = __floats2half2_rn(sre[tid], sim[tid]);
    g_pack[pb + tid + 256] = __floats2half2_rn(sre[tid + 256], sim[tid + 256]);
}

#define TILE  32
#define WIN   52
#define NPAIR 4            // 4 image-pairs = 8 images per block
#define NKG   (NPAIR / 2)  // 2 pair-groups of 2 pairs
#define NBUF  4            // ring buffers (stage distance 2)

// sp[buf][view][loc][kg] : uint4 = (pairA.lo, pairA.hi, pairB.lo, pairB.hi).
// Per-loc stride padded to 3 uint4 (48B) -> bank stride 12 mod 32 (coprime-ish;
// same-bank aliasing needs dloc=8, beyond the 8x4 footprint span).
__global__ void __launch_bounds__(256, 3) backproj_kernel(float* __restrict__ out) {
    __shared__ uint4 sp[NBUF][2][WIN][NKG + 1];
    __shared__ float scos[NV];
    __shared__ float ssin[NV];
    __shared__ int   swin[NV];

    int tid = threadIdx.x;   // 0..255 (1-D launch)

    int g    = blockIdx.z;      // 0..7
    int b    = g >> 2;
    int rblk = g & 3;
    int r0   = rblk * (2 * NPAIR);
    int rp0  = rblk * NPAIR;
    int x0   = blockIdx.x * TILE;
    int y0   = blockIdx.y * TILE;

    float xt = (float)x0 - 255.5f;
    float yt = (float)y0 - 255.5f;

    // Per-view cos/sin + staged-window start (block-uniform).
    if (tid < NV) {
        float s, c;
        sincospif((float)tid * (1.0f / (float)NV), &s, &c);
        scos[tid] = c;
        ssin[tid] = s;
        float tmin = xt * c + yt * s + 255.5f
                   + fminf(31.0f * c, 0.0f) + fminf(31.0f * s, 0.0f);
        int wv = (int)floorf(tmin) - 1;
        swin[tid] = max(0, min(wv, 465));
    }

    // 8x4 warp footprint: warps tiled 2 wide x 4 tall over the 16x16 grid
    int lane = tid & 31;
    int w    = tid >> 5;
    int tx = ((w & 1) << 3) | (lane & 7);   // 0..15
    int ty = ((w >> 1) << 2) | (lane >> 3); // 0..15

    float xb = (float)(x0 + tx) - 255.5f;
    float yb = (float)(y0 + ty) - 255.5f;

    // staging: 104 slots (kg, off) x 2 views -> 208 active threads,
    // each stages ONE view of one slot.
    int sslot = tid >= 104 ? tid - 104 : tid;
    int sview = tid >= 104 ? 1 : 0;
    int skg  = sslot / WIN;            // 0..1
    int soff = sslot - skg * WIN;
    bool stager = (tid < 2 * NKG * WIN);   // tid < 208

    const unsigned* packu = (const unsigned*)g_pack;
    int vrow0 = (b * NV) * NRP + rp0;

    unsigned long long acc[2][2][NPAIR];
    #pragma unroll
    for (int py = 0; py < 2; ++py)
        #pragma unroll
        for (int px = 0; px < 2; ++px)
            #pragma unroll
            for (int k = 0; k < NPAIR; ++k)
                acc[py][px][k] = 0ull;

    const __half2 ones2 = __floats2half2_rn(1.0f, 1.0f);

    __syncthreads();   // tables ready

    // stage view (v + sview) into ring buffer bi
    auto stage = [&](int bi, int v) {
        if (!stager) return;
        int vv = v + sview;
        int wv = swin[vv];
        int pA = (vrow0 + vv * NRP + 2 * skg) * NC;
        int pB = pA + NC;
        int gi = wv + soff;
        uint4 q;
        q.x = packu[pA + gi];
        q.y = packu[pA + gi + 1];
        q.z = packu[pB + gi];
        q.w = packu[pB + gi + 1];
        sp[bi][sview][soff][skg] = q;
    };

    // prologue: stage iterations 0 and 1
    stage(0, 0);
    stage(1, 2);
    __syncthreads();

    for (int it = 0; it < NV / 2; ++it) {
        int buf = it & (NBUF - 1);

        if (it + 2 < NV / 2)
            stage((it + 2) & (NBUF - 1), 2 * it + 4);

        int v = 2 * it;
        float c0 = scos[v],     s0 = ssin[v];
        float c1 = scos[v + 1], s1 = ssin[v + 1];
        int   w0 = swin[v],     w1 = swin[v + 1];

        float t000 = fmaf(xb, c0, fmaf(yb, s0, 255.5f));
        float t001 = fmaf(xb, c1, fmaf(yb, s1, 255.5f));
        float c160 = 16.0f * c0, s160 = 16.0f * s0;
        float c161 = 16.0f * c1, s161 = 16.0f * s1;

        #pragma unroll
        for (int py = 0; py < 2; ++py) {
            #pragma unroll
            for (int px = 0; px < 2; ++px) {
                float ta = t000 + (float)px * c160 + (float)py * s160;
                ta = fminf(fmaxf(ta, 0.0f), 511.0f);
                int ia = __float2int_rd(ta);
                float wa = ta - (float)ia;
                int la = ia - w0;
                __half2 wab  = __float2half2_rn(wa);
                __half2 wab1 = __hsub2(ones2, wab);

                float tb = t001 + (float)px * c161 + (float)py * s161;
                tb = fminf(fmaxf(tb, 0.0f), 511.0f);
                int ib = __float2int_rd(tb);
                float wb = tb - (float)ib;
                int lb = ib - w1;
                __half2 wbb  = __float2half2_rn(wb);
                __half2 wbb1 = __hsub2(ones2, wbb);

                uint4 qa[NKG], qb[NKG];
                #pragma unroll
                for (int kg = 0; kg < NKG; ++kg) qa[kg] = sp[buf][0][la][kg];
                #pragma unroll
                for (int kg = 0; kg < NKG; ++kg) qb[kg] = sp[buf][1][lb][kg];

                #pragma unroll
                for (int kg = 0; kg < NKG; ++kg) {
                    // pair A = 2*kg
                    __half2 vA;
                    vA = __hmul2(*(__half2*)&qa[kg].x, wab1);
                    vA = __hfma2(*(__half2*)&qa[kg].y, wab, vA);
                    vA = __hfma2(*(__half2*)&qb[kg].x, wbb1, vA);
                    vA = __hfma2(*(__half2*)&qb[kg].y, wbb, vA);
                    float2 fA = __half22float2(vA);
                    unsigned long long vpA;
                    asm("mov.b64 %0, {%1, %2};" : "=l"(vpA) : "f"(fA.x), "f"(fA.y));
                    asm("add.rn.f32x2 %0, %0, %1;" : "+l"(acc[py][px][2 * kg]) : "l"(vpA));
                    // pair B = 2*kg+1
                    __half2 vB;
                    vB = __hmul2(*(__half2*)&qa[kg].z, wab1);
                    vB = __hfma2(*(__half2*)&qa[kg].w, wab, vB);
                    vB = __hfma2(*(__half2*)&qb[kg].z, wbb1, vB);
                    vB = __hfma2(*(__half2*)&qb[kg].w, wbb, vB);
                    float2 fB = __half22float2(vB);
                    unsigned long long vpB;
                    asm("mov.b64 %0, {%1, %2};" : "=l"(vpB) : "f"(fB.x), "f"(fB.y));
                    asm("add.rn.f32x2 %0, %0, %1;" : "+l"(acc[py][px][2 * kg + 1]) : "l"(vpB));
                }
            }
        }

        __syncthreads();
    }

    const float outscale = (float)(PI_D / (double)NV);
    #pragma unroll
    for (int k = 0; k < NPAIR; ++k) {
        #pragma unroll
        for (int py = 0; py < 2; ++py) {
            #pragma unroll
            for (int px = 0; px < 2; ++px) {
                int y = y0 + ty + py * 16;
                int x = x0 + tx + px * 16;
                int imgA = r0 + 2 * k;
                float ax, ay;
                asm("mov.b64 {%0, %1}, %2;" : "=f"(ax), "=f"(ay) : "l"(acc[py][px][k]));
                float va = fmaxf(ax * outscale, 0.0f);
                float vb = fmaxf(ay * outscale, 0.0f);
                out[(((b * NR + imgA) * NPIX) + y) * NPIX + x] = va;
                out[(((b * NR + imgA + 1) * NPIX) + y) * NPIX + x] = vb;
            }
        }
    }
}

extern "C" void kernel_launch(void* const* d_in, const int* in_sizes, int n_in,
                              void* d_out, int out_size) {
    const float* sino = (const float*)d_in[0];
    float* out = (float*)d_out;
    (void)in_sizes; (void)n_in; (void)out_size;

    filter_kernel<<<NB * NV * NR / 2, 256>>>(sino);
    dim3 bpGrid(NPIX / TILE, NPIX / TILE, (NB * NR) / (2 * NPAIR));
    backproj_kernel<<<bpGrid, 256>>>(out);   // 1-D 256-thread block
}

// round 13
// speedup vs baseline: 1.0395x; 1.0395x over previous
#include <cuda_runtime.h>
#include <cuda_fp16.h>
#include <math.h>

#define NB 2
#define NV 180
#define NR 32
#define NC 512
#define NPIX 512
#define PI_D 3.14159265358979323846

#define NRP (NR / 2)

// Filtered sinogram, image-pair packed: g_pack[((b*NV+v)*NRP+rp)*NC + i]
//   = half2( filt[b,v,2rp,i], filt[b,v,2rp+1,i] )
// +16 pad: staging reads overrun a row by up to 6 entries (never consumed).
__device__ __half2 g_pack[NB * NV * NRP * NC + 16];

// One block filters TWO consecutive real rows packed as one complex 512-pt FFT.
__global__ void __launch_bounds__(256) filter_kernel(const float* __restrict__ sino) {
    __shared__ float sre[512];
    __shared__ float sim[512];
    __shared__ float twr[256];
    __shared__ float twi[256];

    int tid = threadIdx.x;
    int base = blockIdx.x * 2 * NC;

    {
        float s, c;
        sincospif(-(float)tid * (1.0f / 256.0f), &s, &c);  // exp(-2*pi*i*tid/512)
        twr[tid] = c;
        twi[tid] = s;
    }
    sre[tid]       = sino[base + tid];
    sre[tid + 256] = sino[base + tid + 256];
    sim[tid]       = sino[base + NC + tid];
    sim[tid + 256] = sino[base + NC + tid + 256];
    __syncthreads();

    // ---- DIF forward ----
    {
        int step = 1;
        for (int len = 512; len >= 2; len >>= 1, step <<= 1) {
            int half = len >> 1;
            int grp = tid / half;
            int j = tid - grp * half;
            int i0 = grp * len + j;
            int i1 = i0 + half;
            int tj = j * step;
            float wr = twr[tj], wi = twi[tj];
            float ar = sre[i0], ai = sim[i0];
            float br = sre[i1], bi = sim[i1];
            sre[i0] = ar + br;
            sim[i0] = ai + bi;
            float dr = ar - br, di = ai - bi;
            sre[i1] = dr * wr - di * wi;
            sim[i1] = dr * wi + di * wr;
            if (len >= 128) __syncthreads();
            else __syncwarp();
        }
    }

    // ---- ramp multiply in bitrev slots (warp-local elements 2t, 2t+1) ----
    #pragma unroll
    for (int q = 0; q < 2; ++q) {
        int n = 2 * tid + q;
        int f = (int)(__brev((unsigned)n) >> 23);
        int m = min(f, 512 - f);
        float scale = (float)m * (2.0f / (512.0f * 512.0f));
        sre[n] *= scale;
        sim[n] *= scale;
    }
    __syncwarp();

    // ---- DIT inverse (conj twiddles) ----
    {
        int step = 256;
        for (int len = 2; len <= 512; len <<= 1, step >>= 1) {
            int half = len >> 1;
            int grp = tid / half;
            int j = tid - grp * half;
            int i0 = grp * len + j;
            int i1 = i0 + half;
            int tj = j * step;
            float wr = twr[tj], wi = -twi[tj];
            float ar = sre[i0], ai = sim[i0];
            float br = sre[i1], bi = sim[i1];
            float vr = br * wr - bi * wi;
            float vi = br * wi + bi * wr;
            sre[i0] = ar + vr;
            sim[i0] = ai + vi;
            sre[i1] = ar - vr;
            sim[i1] = ai - vi;
            if (len >= 64) __syncthreads();
            else __syncwarp();
        }
    }

    int pb = blockIdx.x * NC;
    g_pack[pb + tid]       = __floats2half2_rn(sre[tid], sim[tid]);
    g_pack[pb + tid + 256] = __floats2half2_rn(sre[tid + 256], sim[tid + 256]);
}

#define TILE  32
#define WIN   52
#define NPAIR 8            // 8 image-pairs = 16 images per block
#define NKG   (NPAIR / 2)  // 4 pair-groups of 2 pairs
#define NBUF  2            // double buffer; 4 views per buffer slot

// sp[buf][viewIdx(0..3)][loc][kg] : uint4 = (pairA.lo, pairA.hi, pairB.lo, pairB.hi).
// Per-loc stride padded to 5 uint4 (80B) -> bank stride 20 mod 32; same-bank
// aliasing needs dloc=8, beyond the 8-lane phase span (<8).
__global__ void __launch_bounds__(256, 2) backproj_kernel(float* __restrict__ out) {
    __shared__ uint4 sp[NBUF][4][WIN][NKG + 1];
    __shared__ float scos[NV];
    __shared__ float ssin[NV];
    __shared__ int   swin[NV];

    int tid = threadIdx.x;   // 0..255 (1-D launch)

    int g    = blockIdx.z;      // 0..3
    int b    = g >> 1;
    int rblk = g & 1;
    int r0   = rblk * (2 * NPAIR);
    int rp0  = rblk * NPAIR;
    int x0   = blockIdx.x * TILE;
    int y0   = blockIdx.y * TILE;

    float xt = (float)x0 - 255.5f;
    float yt = (float)y0 - 255.5f;

    // Per-view cos/sin + staged-window start (block-uniform).
    if (tid < NV) {
        float s, c;
        sincospif((float)tid * (1.0f / (float)NV), &s, &c);
        scos[tid] = c;
        ssin[tid] = s;
        float tmin = xt * c + yt * s + 255.5f
                   + fminf(31.0f * c, 0.0f) + fminf(31.0f * s, 0.0f);
        int wv = (int)floorf(tmin) - 1;
        swin[tid] = max(0, min(wv, 465));
    }

    // 8x4 warp footprint: warps tiled 2 wide x 4 tall over the 16x16 grid
    int lane = tid & 31;
    int w    = tid >> 5;
    int tx = ((w & 1) << 3) | (lane & 7);   // 0..15
    int ty = ((w >> 1) << 2) | (lane >> 3); // 0..15

    float xb = (float)(x0 + tx) - 255.5f;
    float yb = (float)(y0 + ty) - 255.5f;

    // staging: 208 slots (kg, off); each stager fills its slot for 4 views
    int skg  = tid / WIN;            // 0..4 (valid < 4)
    int soff = tid - skg * WIN;
    bool stager = (tid < NKG * WIN);

    const unsigned* packu = (const unsigned*)g_pack;
    int vrow0 = (b * NV) * NRP + rp0;

    unsigned long long acc[2][2][NPAIR];
    #pragma unroll
    for (int py = 0; py < 2; ++py)
        #pragma unroll
        for (int px = 0; px < 2; ++px)
            #pragma unroll
            for (int k = 0; k < NPAIR; ++k)
                acc[py][px][k] = 0ull;

    const __half2 ones2 = __floats2half2_rn(1.0f, 1.0f);

    __syncthreads();   // tables ready

    // stage views v..v+3 into buffer bi
    auto stage4 = [&](int bi, int v) {
        if (!stager) return;
        #pragma unroll
        for (int u = 0; u < 4; ++u) {
            int vv = v + u;
            int wv = swin[vv];
            int pA = (vrow0 + vv * NRP + 2 * skg) * NC;
            int pB = pA + NC;
            int gi = wv + soff;
            uint4 q;
            q.x = packu[pA + gi];
            q.y = packu[pA + gi + 1];
            q.z = packu[pB + gi];
            q.w = packu[pB + gi + 1];
            sp[bi][u][soff][skg] = q;
        }
    };

    stage4(0, 0);
    __syncthreads();

    for (int it4 = 0; it4 < NV / 4; ++it4) {
        int buf = it4 & 1;

        if (it4 + 1 < NV / 4)
            stage4(buf ^ 1, 4 * it4 + 4);

        // two view-pair compute groups inside one barrier window
        #pragma unroll
        for (int vp = 0; vp < 2; ++vp) {
            int v = 4 * it4 + 2 * vp;
            float c0 = scos[v],     s0 = ssin[v];
            float c1 = scos[v + 1], s1 = ssin[v + 1];
            int   w0 = swin[v],     w1 = swin[v + 1];

            float t000 = fmaf(xb, c0, fmaf(yb, s0, 255.5f));
            float t001 = fmaf(xb, c1, fmaf(yb, s1, 255.5f));
            float c160 = 16.0f * c0, s160 = 16.0f * s0;
            float c161 = 16.0f * c1, s161 = 16.0f * s1;

            #pragma unroll
            for (int py = 0; py < 2; ++py) {
                #pragma unroll
                for (int px = 0; px < 2; ++px) {
                    float ta = t000 + (float)px * c160 + (float)py * s160;
                    ta = fminf(fmaxf(ta, 0.0f), 511.0f);
                    int ia = __float2int_rd(ta);
                    float wa = ta - (float)ia;
                    int la = ia - w0;
                    __half2 wab  = __float2half2_rn(wa);
                    __half2 wab1 = __hsub2(ones2, wab);

                    float tb = t001 + (float)px * c161 + (float)py * s161;
                    tb = fminf(fmaxf(tb, 0.0f), 511.0f);
                    int ib = __float2int_rd(tb);
                    float wb = tb - (float)ib;
                    int lb = ib - w1;
                    __half2 wbb  = __float2half2_rn(wb);
                    __half2 wbb1 = __hsub2(ones2, wbb);

                    uint4 qa[NKG], qb[NKG];
                    #pragma unroll
                    for (int kg = 0; kg < NKG; ++kg) qa[kg] = sp[buf][2 * vp][la][kg];
                    #pragma unroll
                    for (int kg = 0; kg < NKG; ++kg) qb[kg] = sp[buf][2 * vp + 1][lb][kg];

                    #pragma unroll
                    for (int kg = 0; kg < NKG; ++kg) {
                        // pair A = 2*kg
                        __half2 vA;
                        vA = __hmul2(*(__half2*)&qa[kg].x, wab1);
                        vA = __hfma2(*(__half2*)&qa[kg].y, wab, vA);
                        vA = __hfma2(*(__half2*)&qb[kg].x, wbb1, vA);
                        vA = __hfma2(*(__half2*)&qb[kg].y, wbb, vA);
                        float2 fA = __half22float2(vA);
                        unsigned long long vpA;
                        asm("mov.b64 %0, {%1, %2};" : "=l"(vpA) : "f"(fA.x), "f"(fA.y));
                        asm("add.rn.f32x2 %0, %0, %1;" : "+l"(acc[py][px][2 * kg]) : "l"(vpA));
                        // pair B = 2*kg+1
                        __half2 vB;
                        vB = __hmul2(*(__half2*)&qa[kg].z, wab1);
                        vB = __hfma2(*(__half2*)&qa[kg].w, wab, vB);
                        vB = __hfma2(*(__half2*)&qb[kg].z, wbb1, vB);
                        vB = __hfma2(*(__half2*)&qb[kg].w, wbb, vB);
                        float2 fB = __half22float2(vB);
                        unsigned long long vpB;
                        asm("mov.b64 %0, {%1, %2};" : "=l"(vpB) : "f"(fB.x), "f"(fB.y));
                        asm("add.rn.f32x2 %0, %0, %1;" : "+l"(acc[py][px][2 * kg + 1]) : "l"(vpB));
                    }
                }
            }
        }

        __syncthreads();
    }

    const float outscale = (float)(PI_D / (double)NV);
    #pragma unroll
    for (int k = 0; k < NPAIR; ++k) {
        #pragma unroll
        for (int py = 0; py < 2; ++py) {
            #pragma unroll
            for (int px = 0; px < 2; ++px) {
                int y = y0 + ty + py * 16;
                int x = x0 + tx + px * 16;
                int imgA = r0 + 2 * k;
                float ax, ay;
                asm("mov.b64 {%0, %1}, %2;" : "=f"(ax), "=f"(ay) : "l"(acc[py][px][k]));
                float va = fmaxf(ax * outscale, 0.0f);
                float vb = fmaxf(ay * outscale, 0.0f);
                out[(((b * NR + imgA) * NPIX) + y) * NPIX + x] = va;
                out[(((b * NR + imgA + 1) * NPIX) + y) * NPIX + x] = vb;
            }
        }
    }
}

extern "C" void kernel_launch(void* const* d_in, const int* in_sizes, int n_in,
                              void* d_out, int out_size) {
    const float* sino = (const float*)d_in[0];
    float* out = (float*)d_out;
    (void)in_sizes; (void)n_in; (void)out_size;

    filter_kernel<<<NB * NV * NR / 2, 256>>>(sino);
    dim3 bpGrid(NPIX / TILE, NPIX / TILE, (NB * NR) / (2 * NPAIR));
    backproj_kernel<<<bpGrid, 256>>>(out);   // 1-D 256-thread block
}

// round 15
// speedup vs baseline: 1.0794x; 1.0384x over previous
#include <cuda_runtime.h>
#include <cuda_fp16.h>
#include <math.h>

#define NB 2
#define NV 180
#define NR 32
#define NC 512
#define NPIX 512
#define PI_D 3.14159265358979323846

#define NRP (NR / 2)

// Filtered sinogram, image-pair packed: g_pack[((b*NV+v)*NRP+rp)*NC + i]
//   = half2( filt[b,v,2rp,i], filt[b,v,2rp+1,i] )
// +16 pad: staging reads overrun a row by up to 6 entries (never consumed).
__device__ __half2 g_pack[NB * NV * NRP * NC + 16];

// One block filters FOUR consecutive real rows as TWO packed complex 512-pt
// FFTs (rows 0,1 -> FFT0 re/im; rows 2,3 -> FFT1 re/im). Each thread runs the
// same butterfly for both FFTs -> 2x ILP, barriers amortized, half the blocks.
// DIF forward -> ramp in bit-reversed slots -> DIT inverse (conj twiddles).
__global__ void __launch_bounds__(256) filter_kernel(const float* __restrict__ sino) {
    __shared__ float sre[1024];   // [f*512 + i]
    __shared__ float sim[1024];
    __shared__ float twr[256];
    __shared__ float twi[256];

    int tid = threadIdx.x;
    int base = blockIdx.x * 4 * NC;   // 4 rows per block

    {
        float s, c;
        sincospif(-(float)tid * (1.0f / 256.0f), &s, &c);  // exp(-2*pi*i*tid/512)
        twr[tid] = c;
        twi[tid] = s;
    }
    // FFT0: rows 0 (re), 1 (im); FFT1: rows 2 (re), 3 (im)
    sre[tid]             = sino[base + tid];
    sre[tid + 256]       = sino[base + tid + 256];
    sim[tid]             = sino[base + NC + tid];
    sim[tid + 256]       = sino[base + NC + tid + 256];
    sre[512 + tid]       = sino[base + 2 * NC + tid];
    sre[512 + tid + 256] = sino[base + 2 * NC + tid + 256];
    sim[512 + tid]       = sino[base + 3 * NC + tid];
    sim[512 + tid + 256] = sino[base + 3 * NC + tid + 256];
    __syncthreads();

    // ---- DIF forward ----
    {
        int step = 1;
        for (int len = 512; len >= 2; len >>= 1, step <<= 1) {
            int half = len >> 1;
            int grp = tid / half;
            int j = tid - grp * half;
            int i0 = grp * len + j;
            int i1 = i0 + half;
            int tj = j * step;
            float wr = twr[tj], wi = twi[tj];
            #pragma unroll
            for (int f = 0; f < 2; ++f) {
                int o = f << 9;
                float ar = sre[o + i0], ai = sim[o + i0];
                float br = sre[o + i1], bi = sim[o + i1];
                sre[o + i0] = ar + br;
                sim[o + i0] = ai + bi;
                float dr = ar - br, di = ai - bi;
                sre[o + i1] = dr * wr - di * wi;
                sim[o + i1] = dr * wi + di * wr;
            }
            if (len >= 128) __syncthreads();
            else __syncwarp();
        }
    }

    // ---- ramp multiply in bitrev slots (warp-local elements 2t, 2t+1) ----
    #pragma unroll
    for (int q = 0; q < 2; ++q) {
        int n = 2 * tid + q;
        int fb = (int)(__brev((unsigned)n) >> 23);
        int m = min(fb, 512 - fb);
        float scale = (float)m * (2.0f / (512.0f * 512.0f));
        #pragma unroll
        for (int f = 0; f < 2; ++f) {
            int o = f << 9;
            sre[o + n] *= scale;
            sim[o + n] *= scale;
        }
    }
    __syncwarp();

    // ---- DIT inverse (conj twiddles) ----
    {
        int step = 256;
        for (int len = 2; len <= 512; len <<= 1, step >>= 1) {
            int half = len >> 1;
            int grp = tid / half;
            int j = tid - grp * half;
            int i0 = grp * len + j;
            int i1 = i0 + half;
            int tj = j * step;
            float wr = twr[tj], wi = -twi[tj];
            #pragma unroll
            for (int f = 0; f < 2; ++f) {
                int o = f << 9;
                float ar = sre[o + i0], ai = sim[o + i0];
                float br = sre[o + i1], bi = sim[o + i1];
                float vr = br * wr - bi * wi;
                float vi = br * wi + bi * wr;
                sre[o + i0] = ar + vr;
                sim[o + i0] = ai + vi;
                sre[o + i1] = ar - vr;
                sim[o + i1] = ai - vi;
            }
            if (len >= 64) __syncthreads();
            else __syncwarp();
        }
    }

    // pair p = 2*blockIdx.x + f
    int pb = blockIdx.x * 2 * NC;
    g_pack[pb + tid]            = __floats2half2_rn(sre[tid], sim[tid]);
    g_pack[pb + tid + 256]      = __floats2half2_rn(sre[tid + 256], sim[tid + 256]);
    g_pack[pb + NC + tid]       = __floats2half2_rn(sre[512 + tid], sim[512 + tid]);
    g_pack[pb + NC + tid + 256] = __floats2half2_rn(sre[512 + tid + 256], sim[512 + tid + 256]);
}

#define TILE  32
#define WIN   52
#define NPAIR 8            // 8 image-pairs = 16 images per block
#define NKG   (NPAIR / 2)  // 4 pair-groups of 2 pairs
#define NBUF  4            // ring buffers (stage distance 2)

// sp[buf][view][loc][kg] : uint4 = (pairA.lo, pairA.hi, pairB.lo, pairB.hi).
// Per-loc stride padded to 5 uint4 (80B) -> bank stride 20 mod 32.
__global__ void __launch_bounds__(256, 2) backproj_kernel(float* __restrict__ out) {
    __shared__ uint4 sp[NBUF][2][WIN][NKG + 1];
    __shared__ float scos[NV];
    __shared__ float ssin[NV];
    __shared__ int   swin[NV];

    int tid = threadIdx.x;   // 0..255 (1-D launch)

    int g    = blockIdx.z;      // 0..3
    int b    = g >> 1;
    int rblk = g & 1;
    int r0   = rblk * (2 * NPAIR);
    int rp0  = rblk * NPAIR;
    int x0   = blockIdx.x * TILE;
    int y0   = blockIdx.y * TILE;

    float xt = (float)x0 - 255.5f;
    float yt = (float)y0 - 255.5f;

    // Precompute per-view cos/sin + staged-window start (block-uniform).
    if (tid < NV) {
        float s, c;
        sincospif((float)tid * (1.0f / (float)NV), &s, &c);
        scos[tid] = c;
        ssin[tid] = s;
        float tmin = xt * c + yt * s + 255.5f
                   + fminf(31.0f * c, 0.0f) + fminf(31.0f * s, 0.0f);
        int wv = (int)floorf(tmin) - 1;
        swin[tid] = max(0, min(wv, 465));
    }

    // 8x4 warp footprint: warps tiled 2 wide x 4 tall over the 16x16 grid
    int lane = tid & 31;
    int w    = tid >> 5;
    int tx = ((w & 1) << 3) | (lane & 7);   // 0..15
    int ty = ((w >> 1) << 2) | (lane >> 3); // 0..15

    float xb = (float)(x0 + tx) - 255.5f;
    float yb = (float)(y0 + ty) - 255.5f;

    // staging: 208 slots (kg, off); each thread handles both views of one slot
    int skg  = tid / WIN;            // 0..4 (valid < 4)
    int soff = tid - skg * WIN;
    bool stager = (tid < NKG * WIN);

    const unsigned* packu = (const unsigned*)g_pack;
    int vrow0 = (b * NV) * NRP + rp0;

    unsigned long long acc[2][2][NPAIR];
    #pragma unroll
    for (int py = 0; py < 2; ++py)
        #pragma unroll
        for (int px = 0; px < 2; ++px)
            #pragma unroll
            for (int k = 0; k < NPAIR; ++k)
                acc[py][px][k] = 0ull;

    const __half2 ones2 = __floats2half2_rn(1.0f, 1.0f);

    __syncthreads();   // tables ready (also makes swin visible to stagers)

    // stage views v, v+1 into ring buffer bi (windows from swin[])
    auto stage = [&](int bi, int v) {
        if (!stager) return;
        int wa = swin[v], wb = swin[v + 1];
        int pA = (vrow0 + v * NRP + 2 * skg) * NC;       // pair 2*skg, view v
        int pB = pA + NC;
        {
            int gi = wa + soff;
            uint4 q;
            q.x = packu[pA + gi];
            q.y = packu[pA + gi + 1];
            q.z = packu[pB + gi];
            q.w = packu[pB + gi + 1];
            sp[bi][0][soff][skg] = q;
        }
        {
            int pA1 = pA + NRP * NC;
            int pB1 = pB + NRP * NC;
            int gi = wb + soff;
            uint4 q;
            q.x = packu[pA1 + gi];
            q.y = packu[pA1 + gi + 1];
            q.z = packu[pB1 + gi];
            q.w = packu[pB1 + gi + 1];
            sp[bi][1][soff][skg] = q;
        }
    };

    // prologue: stage iterations 0 and 1
    stage(0, 0);
    stage(1, 2);
    __syncthreads();

    for (int it = 0; it < NV / 2; ++it) {
        int buf = it & (NBUF - 1);

        if (it + 2 < NV / 2)
            stage((it + 2) & (NBUF - 1), 2 * it + 4);

        int v = 2 * it;
        float c0 = scos[v],     s0 = ssin[v];
        float c1 = scos[v + 1], s1 = ssin[v + 1];
        int   w0 = swin[v],     w1 = swin[v + 1];

        float t000 = fmaf(xb, c0, fmaf(yb, s0, 255.5f));
        float t001 = fmaf(xb, c1, fmaf(yb, s1, 255.5f));
        float c160 = 16.0f * c0, s160 = 16.0f * s0;
        float c161 = 16.0f * c1, s161 = 16.0f * s1;

        #pragma unroll
        for (int py = 0; py < 2; ++py) {
            #pragma unroll
            for (int px = 0; px < 2; ++px) {
                float ta = t000 + (float)px * c160 + (float)py * s160;
                ta = fminf(fmaxf(ta, 0.0f), 511.0f);
                int ia = __float2int_rd(ta);
                float wa = ta - (float)ia;
                int la = ia - w0;
                __half2 wab  = __float2half2_rn(wa);
                __half2 wab1 = __hsub2(ones2, wab);

                float tb = t001 + (float)px * c161 + (float)py * s161;
                tb = fminf(fmaxf(tb, 0.0f), 511.0f);
                int ib = __float2int_rd(tb);
                float wb = tb - (float)ib;
                int lb = ib - w1;
                __half2 wbb  = __float2half2_rn(wb);
                __half2 wbb1 = __hsub2(ones2, wbb);

                // hoist all 8 loads (both views x 4 kg) -> deep MLP
                uint4 qa[NKG], qb[NKG];
                #pragma unroll
                for (int kg = 0; kg < NKG; ++kg) qa[kg] = sp[buf][0][la][kg];
                #pragma unroll
                for (int kg = 0; kg < NKG; ++kg) qb[kg] = sp[buf][1][lb][kg];

                #pragma unroll
                for (int kg = 0; kg < NKG; ++kg) {
                    // pair A = 2*kg
                    __half2 vA;
                    vA = __hmul2(*(__half2*)&qa[kg].x, wab1);
                    vA = __hfma2(*(__half2*)&qa[kg].y, wab, vA);
                    vA = __hfma2(*(__half2*)&qb[kg].x, wbb1, vA);
                    vA = __hfma2(*(__half2*)&qb[kg].y, wbb, vA);
                    float2 fA = __half22float2(vA);
                    unsigned long long vpA;
                    asm("mov.b64 %0, {%1, %2};" : "=l"(vpA) : "f"(fA.x), "f"(fA.y));
                    asm("add.rn.f32x2 %0, %0, %1;" : "+l"(acc[py][px][2 * kg]) : "l"(vpA));
                    // pair B = 2*kg+1
                    __half2 vB;
                    vB = __hmul2(*(__half2*)&qa[kg].z, wab1);
                    vB = __hfma2(*(__half2*)&qa[kg].w, wab, vB);
                    vB = __hfma2(*(__half2*)&qb[kg].z, wbb1, vB);
                    vB = __hfma2(*(__half2*)&qb[kg].w, wbb, vB);
                    float2 fB = __half22float2(vB);
                    unsigned long long vpB;
                    asm("mov.b64 %0, {%1, %2};" : "=l"(vpB) : "f"(fB.x), "f"(fB.y));
                    asm("add.rn.f32x2 %0, %0, %1;" : "+l"(acc[py][px][2 * kg + 1]) : "l"(vpB));
                }
            }
        }

        __syncthreads();
    }

    const float outscale = (float)(PI_D / (double)NV);
    #pragma unroll
    for (int k = 0; k < NPAIR; ++k) {
        #pragma unroll
        for (int py = 0; py < 2; ++py) {
            #pragma unroll
            for (int px = 0; px < 2; ++px) {
                int y = y0 + ty + py * 16;
                int x = x0 + tx + px * 16;
                int imgA = r0 + 2 * k;
                float ax, ay;
                asm("mov.b64 {%0, %1}, %2;" : "=f"(ax), "=f"(ay) : "l"(acc[py][px][k]));
                float va = fmaxf(ax * outscale, 0.0f);
                float vb = fmaxf(ay * outscale, 0.0f);
                out[(((b * NR + imgA) * NPIX) + y) * NPIX + x] = va;
                out[(((b * NR + imgA + 1) * NPIX) + y) * NPIX + x] = vb;
            }
        }
    }
}

extern "C" void kernel_launch(void* const* d_in, const int* in_sizes, int n_in,
                              void* d_out, int out_size) {
    const float* sino = (const float*)d_in[0];
    float* out = (float*)d_out;
    (void)in_sizes; (void)n_in; (void)out_size;

    filter_kernel<<<NB * NV * NR / 4, 256>>>(sino);   // 4 rows (2 FFTs) per block
    dim3 bpGrid(NPIX / TILE, NPIX / TILE, (NB * NR) / (2 * NPAIR));
    backproj_kernel<<<bpGrid, 256>>>(out);   // 1-D 256-thread block
}